// round 13
// baseline (speedup 1.0000x reference)
#include <cuda_runtime.h>
#include <math.h>

#define S_SEQ 2048
#define NB 64
#define NH 512
#define NF 512
#define NGATE 4
#define REC_THREADS 256

#define NGROUP 8                 // batch groups (8 batches each)
#define GB 8                     // batches per group
#define CTA_PER_GROUP 32         // 32 CTAs x 16 h-cols = 2048 n-cols
#define NCTA_REC 128             // each CTA serves 2 groups (chains A/B)
#define BAR_TARGET (CTA_PER_GROUP * 4)   // 128 warp arrivals per group-step

// Scratch: pre-activations xpre[s][gate][b][h] (1.07 GB), h ping-pong,
// per-step barrier slots per group (self-cleaning).
__device__ float    g_xpre[(size_t)S_SEQ * NGATE * NB * NH];
__device__ float    g_hbuf[2][NB * NH];
__device__ unsigned g_bar[NGROUP * S_SEQ];

// -------------------------------------------------------------------------
// tf32 helpers
// -------------------------------------------------------------------------
__device__ __forceinline__ float to_tf32(float f) {
    float r;
    asm("cvt.rna.tf32.f32 %0, %1;" : "=f"(r) : "f"(f));
    return r;
}

__device__ __forceinline__ void mma_tf32(float4& c, const float* a, const float* b) {
    asm volatile(
        "mma.sync.aligned.m16n8k8.row.col.f32.tf32.tf32.f32 "
        "{%0,%1,%2,%3}, {%4,%5,%6,%7}, {%8,%9}, {%0,%1,%2,%3};"
        : "+f"(c.x), "+f"(c.y), "+f"(c.z), "+f"(c.w)
        : "r"(__float_as_uint(a[0])), "r"(__float_as_uint(a[1])),
          "r"(__float_as_uint(a[2])), "r"(__float_as_uint(a[3])),
          "r"(__float_as_uint(b[0])), "r"(__float_as_uint(b[1])));
}

// -------------------------------------------------------------------------
// Input projection v2 (unchanged from Round 6).
// -------------------------------------------------------------------------
struct ProjPtrs {
    const float* w[4];
    const float* bx[4];
    const float* bh[4];
};

#define PROJ_THREADS 128
#define AF_FLOATS 4224
#define BS_FLOATS 4352
#define PBUF_FLOATS (AF_FLOATS + BS_FLOATS)
#define PROJ_SMEM_BYTES (2 * PBUF_FLOATS * 4)   // 68608 B

__global__ __launch_bounds__(PROJ_THREADS, 2)
void proj_tf32_kernel(const float* __restrict__ x, ProjPtrs p) {
    extern __shared__ float psm[];

    const int tid  = threadIdx.x;
    const int lane = tid & 31;
    const int wid  = tid >> 5;
    const int wm   = wid & 1;
    const int wn   = wid >> 1;
    const int gq   = lane >> 2;
    const int tq   = lane & 3;

    const int nTile = blockIdx.x;
    const int mTile = blockIdx.y;
    const int r0    = mTile * 128;
    const int g     = nTile >> 2;
    const int hc0   = (nTile & 3) * 128;
    const float* W  = p.w[g];

    float4 ga[8], gb[8];

    auto load_tile = [&](int k0) {
#pragma unroll
        for (int i = 0; i < 8; ++i) {
            const int e  = tid + i * PROJ_THREADS;
            const int ar = e >> 3, akq = e & 7;
            ga[i] = *reinterpret_cast<const float4*>(
                x + (size_t)(r0 + ar) * NF + k0 + akq * 4);
            const int br = e >> 5, bcq = e & 31;
            gb[i] = *reinterpret_cast<const float4*>(
                W + (size_t)(k0 + br) * NH + hc0 + bcq * 4);
        }
    };

    auto stage_tile = [&](int buf) {
        float* A_f = psm + buf * PBUF_FLOATS;
        float* B_s = A_f + AF_FLOATS;
#pragma unroll
        for (int i = 0; i < 8; ++i) {
            const int e   = tid + i * PROJ_THREADS;
            const int ar  = e >> 3, akq = e & 7;
            const int wmS = ar >> 6;
            const int r6  = ar & 63;
            const int mtS = r6 >> 4;
            const int half = (r6 >> 3) & 1;
            const int gqS  = r6 & 7;
            const int kcS  = akq >> 1;
            const int quad = 2 * (akq & 1) + half;
            const int base = ((wmS * 4 + mtS) * 4 + kcS) * 132 + gqS * 16 + quad;
            A_f[base + 0]  = to_tf32(ga[i].x);
            A_f[base + 4]  = to_tf32(ga[i].y);
            A_f[base + 8]  = to_tf32(ga[i].z);
            A_f[base + 12] = to_tf32(ga[i].w);

            const int br = e >> 5, bcq = e & 31;
            B_s[br * 136 + bcq * 4 + 0] = to_tf32(gb[i].x);
            B_s[br * 136 + bcq * 4 + 1] = to_tf32(gb[i].y);
            B_s[br * 136 + bcq * 4 + 2] = to_tf32(gb[i].z);
            B_s[br * 136 + bcq * 4 + 3] = to_tf32(gb[i].w);
        }
    };

    float4 acc[4][8];
#pragma unroll
    for (int mt = 0; mt < 4; ++mt)
#pragma unroll
        for (int nt = 0; nt < 8; ++nt)
            acc[mt][nt] = make_float4(0.f, 0.f, 0.f, 0.f);

    load_tile(0);
    stage_tile(0);

    for (int it = 0; it < NF / 32; ++it) {
        __syncthreads();
        if (it + 1 < NF / 32) load_tile((it + 1) * 32);

        const float* A_f = psm + (it & 1) * PBUF_FLOATS;
        const float* B_s = A_f + AF_FLOATS;
#pragma unroll
        for (int kc = 0; kc < 4; ++kc) {
            float4 afv[4];
#pragma unroll
            for (int mt = 0; mt < 4; ++mt)
                afv[mt] = *reinterpret_cast<const float4*>(
                    &A_f[((wm * 4 + mt) * 4 + kc) * 132 + lane * 4]);
            float bf[8][2];
            const int kb = kc * 8;
#pragma unroll
            for (int nt = 0; nt < 8; ++nt) {
                const int cb = wn * 64 + nt * 8 + gq;
                bf[nt][0] = B_s[(kb + tq) * 136 + cb];
                bf[nt][1] = B_s[(kb + tq + 4) * 136 + cb];
            }
#pragma unroll
            for (int mt = 0; mt < 4; ++mt)
#pragma unroll
                for (int nt = 0; nt < 8; ++nt)
                    mma_tf32(acc[mt][nt], reinterpret_cast<float*>(&afv[mt]), bf[nt]);
        }

        if (it + 1 < NF / 32) stage_tile((it + 1) & 1);
    }

#pragma unroll
    for (int nt = 0; nt < 8; ++nt) {
        const int colb = hc0 + wn * 64 + nt * 8 + tq * 2;
        const float bias0 = p.bx[g][colb]     + p.bh[g][colb];
        const float bias1 = p.bx[g][colb + 1] + p.bh[g][colb + 1];
#pragma unroll
        for (int mt = 0; mt < 4; ++mt) {
            const int r1 = r0 + wm * 64 + mt * 16 + gq;
            const int r2 = r1 + 8;
            {
                const int bb = r1 >> 11, s = r1 & 2047;
                const size_t base = ((size_t)(s * 4 + g) * NB + bb) * NH;
                *reinterpret_cast<float2*>(&g_xpre[base + colb]) =
                    make_float2(acc[mt][nt].x + bias0, acc[mt][nt].y + bias1);
            }
            {
                const int bb = r2 >> 11, s = r2 & 2047;
                const size_t base = ((size_t)(s * 4 + g) * NB + bb) * NH;
                *reinterpret_cast<float2*>(&g_xpre[base + colb]) =
                    make_float2(acc[mt][nt].z + bias0, acc[mt][nt].w + bias1);
            }
        }
    }
}

// -------------------------------------------------------------------------
// Dual-chain tensor-core recurrent kernel.
// 128 CTAs; CTA (gp, cidx) serves groups 2gp (chain A) and 2gp+1 (chain B),
// each 8 batches, with the SAME 16 h-cols (W_h breg shared). Per iteration
// both chains advance one step, interleaved so each chain's barrier
// round-trip is overlapped by the other chain's compute.
// m16 mma with rows 8-15 zeroed (af1=af3=0). acc registers reused across
// chains (disjoint live ranges).
// -------------------------------------------------------------------------
#define SLICE_STRIDE 68
#define SLICE_FLOATS (GB * SLICE_STRIDE)         // 544 per warp
#define RED_STRIDE 68
#define RED_CHUNK (GB * RED_STRIDE)              // 544 per warp per chain
#define RED_FLOATS (16 * RED_CHUNK)              // 2 chains x 8 warps
#define REC_SMEM_BYTES ((8 * SLICE_FLOATS + RED_FLOATS) * 4)   // 52224 B

__device__ __forceinline__ float fsig(float v) {
    return __fdividef(1.f, 1.f + __expf(-v));
}
__device__ __forceinline__ float ftanh(float v) {
    return 1.f - __fdividef(2.f, __expf(2.f * v) + 1.f);
}

__global__ __launch_bounds__(REC_THREADS, 1)
void rec_dual_kernel(const float* __restrict__ w_hi, const float* __restrict__ w_hf,
                     const float* __restrict__ w_hg, const float* __restrict__ w_ho,
                     float* __restrict__ out) {
    extern __shared__ float sm[];
    float* red = sm + 8 * SLICE_FLOATS;   // [chain*8 + warp][row 8][col 64 pad 68]

    const int tid   = threadIdx.x;
    const int lane  = tid & 31;
    const int wid   = tid >> 5;
    const int gq    = lane >> 2;
    const int tq    = lane & 3;
    const int gp    = blockIdx.x >> 5;      // group pair 0..3
    const int cidx  = blockIdx.x & 31;
    const int c0    = cidx * 16;
    const int grpA  = 2 * gp;
    const int grpB  = 2 * gp + 1;
    unsigned* barA  = g_bar + grpA * S_SEQ;
    unsigned* barB  = g_bar + grpB * S_SEQ;
    const bool janitor = (cidx == 0 && tid == 0);

    float* slice = sm + wid * SLICE_FLOATS;   // reused by both chains

    // ---- persistent W_h B-fragments in registers (shared by both chains) ---
    float breg[8][8][2];
    {
        const float* wh[4] = {w_hi, w_hf, w_hg, w_ho};
#pragma unroll
        for (int nt = 0; nt < 8; ++nt) {
            const int n  = nt * 8 + gq;
            const float* wp = wh[n & 3] + c0 + (n >> 2);
#pragma unroll
            for (int kc = 0; kc < 8; ++kc) {
                const int k0 = wid * 64 + kc * 8 + tq;
                breg[kc][nt][0] = to_tf32(wp[(size_t)k0 * NH]);
                breg[kc][nt][1] = to_tf32(wp[(size_t)(k0 + 4) * NH]);
            }
        }
    }

    // ---- epilogue ownership: chain = tid>>7; (eb, ejj) within chain --------
    const int chain = tid >> 7;               // 0 = A (warps 0-3), 1 = B
    const int eb    = (tid >> 4) & 7;         // local batch 0..7
    const int ejj   = tid & 15;               // local h-col 0..15
    const int gmy   = 2 * gp + chain;
    const int gbat  = gmy * GB + eb;          // global batch
    const int ej    = c0 + ejj;               // global h-col
    unsigned* barMy = chain ? barB : barA;
    float cst = 0.f;

    // per-chain helpers ------------------------------------------------------
    auto stage_h = [&](const float* hsrc, int grp) {
#pragma unroll
        for (int it = 0; it < 4; ++it) {
            const int i   = it * 32 + lane;    // 0..127
            const int row = i >> 4;            // 0..7
            const int c4  = i & 15;
            float4 hv = __ldcg(reinterpret_cast<const float4*>(
                hsrc + (size_t)(grp * GB + row) * NH + wid * 64 + c4 * 4));
            *reinterpret_cast<float4*>(&slice[row * SLICE_STRIDE + c4 * 4]) = hv;
        }
        __syncwarp();
    };

    float4 acc[8];   // reused across chains (disjoint live ranges)

    auto h_mma = [&]() {
#pragma unroll
        for (int nt = 0; nt < 8; ++nt) acc[nt] = make_float4(0.f, 0.f, 0.f, 0.f);
#pragma unroll
        for (int kc = 0; kc < 8; ++kc) {
            const int kcol = kc * 8 + tq;
            float af[4];
            af[0] = slice[gq * SLICE_STRIDE + kcol];
            af[1] = 0.f;                          // rows 8-15 unused
            af[2] = slice[gq * SLICE_STRIDE + kcol + 4];
            af[3] = 0.f;
#pragma unroll
            for (int nt = 0; nt < 8; ++nt)
                mma_tf32(acc[nt], af, breg[kc][nt]);
        }
    };

    auto dump = [&](int ch) {
        float* rw = red + (ch * 8 + wid) * RED_CHUNK;
#pragma unroll
        for (int nt = 0; nt < 8; ++nt) {
            const int col = nt * 8 + tq * 2;
            *reinterpret_cast<float2*>(&rw[gq * RED_STRIDE + col]) =
                make_float2(acc[nt].x, acc[nt].y);
        }
    };

    auto poll = [&](unsigned* slot) {
        unsigned v;
        do {
            asm volatile("ld.acquire.gpu.global.u32 %0, [%1];"
                         : "=r"(v) : "l"(slot) : "memory");
        } while (v < (unsigned)BAR_TARGET);
    };

    for (int t = 0; t < S_SEQ; ++t) {
        // prefetch my chain's x pre-activations (consumed in epilogue)
        float xv[4];
#pragma unroll
        for (int g = 0; g < 4; ++g)
            xv[g] = __ldcg(&g_xpre[(((size_t)t * 4 + g) * NB + gbat) * NH + ej]);

        if (t > 0) {
            const float* hsrc = g_hbuf[t & 1];

            // ---- chain A: wait, stage, mma, dump -----------------------------
            poll(barA + (t - 1));
            if (janitor && t >= 2)
                asm volatile("st.relaxed.gpu.global.u32 [%0], %1;"
                             :: "l"(barA + (t - 2)), "r"(0u) : "memory");
            stage_h(hsrc, grpA);
            h_mma();
            __syncwarp();          // mma's LDS done before slice overwrite
            dump(0);

            // ---- chain B: wait, stage, mma, dump -----------------------------
            poll(barB + (t - 1));
            if (janitor && t >= 2)
                asm volatile("st.relaxed.gpu.global.u32 [%0], %1;"
                             :: "l"(barB + (t - 2)), "r"(0u) : "memory");
            stage_h(hsrc, grpB);
            h_mma();
            __syncwarp();
            dump(1);
        }
        __syncthreads();

        // ---- reduce 8 warp-partials for my (chain, batch, h-col) -------------
        float s0 = 0.f, s1 = 0.f, s2 = 0.f, s3 = 0.f;
        if (t > 0) {
#pragma unroll
            for (int w = 0; w < 8; ++w) {
                const float4 v = *reinterpret_cast<const float4*>(
                    &red[(chain * 8 + w) * RED_CHUNK + eb * RED_STRIDE + ejj * 4]);
                s0 += v.x; s1 += v.y; s2 += v.z; s3 += v.w;
            }
        }

        const float ig = fsig(s0 + xv[0]);
        const float fg = fsig(s1 + xv[1]);
        const float gg = ftanh(s2 + xv[2]);
        const float og = fsig(s3 + xv[3]);
        cst = fg * cst + ig * gg;
        const float hnew = og * ftanh(cst);

        if (t < S_SEQ - 1) {
            g_hbuf[(t + 1) & 1][gbat * NH + ej] = to_tf32(hnew);
            __syncwarp();
            if (lane == 0) {
                asm volatile("red.release.gpu.global.add.u32 [%0], %1;"
                             :: "l"(barMy + t), "r"(1u) : "memory");
            }
        } else {
            out[gbat * NH + ej]           = hnew;
            out[NB * NH + gbat * NH + ej] = cst;
        }
    }

    // ---- cleanup: extra arrival on slot S_SEQ-1 per chain, janitor zeroes ---
    __syncwarp();
    if (lane == 0)
        asm volatile("red.release.gpu.global.add.u32 [%0], %1;"
                     :: "l"(barMy + (S_SEQ - 1)), "r"(1u) : "memory");
    if (janitor) {
        unsigned v;
        do {
            asm volatile("ld.acquire.gpu.global.u32 %0, [%1];"
                         : "=r"(v) : "l"(barA + (S_SEQ - 1)) : "memory");
        } while (v < (unsigned)BAR_TARGET);
        do {
            asm volatile("ld.acquire.gpu.global.u32 %0, [%1];"
                         : "=r"(v) : "l"(barB + (S_SEQ - 1)) : "memory");
        } while (v < (unsigned)BAR_TARGET);
        asm volatile("st.relaxed.gpu.global.u32 [%0], %1;"
                     :: "l"(barA + (S_SEQ - 2)), "r"(0u) : "memory");
        asm volatile("st.relaxed.gpu.global.u32 [%0], %1;"
                     :: "l"(barA + (S_SEQ - 1)), "r"(0u) : "memory");
        asm volatile("st.relaxed.gpu.global.u32 [%0], %1;"
                     :: "l"(barB + (S_SEQ - 2)), "r"(0u) : "memory");
        asm volatile("st.relaxed.gpu.global.u32 [%0], %1;"
                     :: "l"(barB + (S_SEQ - 1)), "r"(0u) : "memory");
    }
}

// -------------------------------------------------------------------------
extern "C" void kernel_launch(void* const* d_in, const int* in_sizes, int n_in,
                              void* d_out, int out_size) {
    const float* x    = (const float*)d_in[0];
    const float* w_ii = (const float*)d_in[1];
    const float* b_ii = (const float*)d_in[2];
    const float* w_hi = (const float*)d_in[3];
    const float* b_hi = (const float*)d_in[4];
    const float* w_if = (const float*)d_in[5];
    const float* b_if = (const float*)d_in[6];
    const float* w_hf = (const float*)d_in[7];
    const float* b_hf = (const float*)d_in[8];
    const float* w_ig = (const float*)d_in[9];
    const float* b_ig = (const float*)d_in[10];
    const float* w_hg = (const float*)d_in[11];
    const float* b_hg = (const float*)d_in[12];
    const float* w_io = (const float*)d_in[13];
    const float* b_io = (const float*)d_in[14];
    const float* w_ho = (const float*)d_in[15];
    const float* b_ho = (const float*)d_in[16];

    cudaFuncSetAttribute(proj_tf32_kernel, cudaFuncAttributeMaxDynamicSharedMemorySize,
                         PROJ_SMEM_BYTES);
    cudaFuncSetAttribute(rec_dual_kernel, cudaFuncAttributeMaxDynamicSharedMemorySize,
                         REC_SMEM_BYTES);

    ProjPtrs p;
    p.w[0] = w_ii; p.w[1] = w_if; p.w[2] = w_ig; p.w[3] = w_io;
    p.bx[0] = b_ii; p.bx[1] = b_if; p.bx[2] = b_ig; p.bx[3] = b_io;
    p.bh[0] = b_hi; p.bh[1] = b_hf; p.bh[2] = b_hg; p.bh[3] = b_ho;
    proj_tf32_kernel<<<dim3(16, 1024), PROJ_THREADS, PROJ_SMEM_BYTES>>>(x, p);

    rec_dual_kernel<<<NCTA_REC, REC_THREADS, REC_SMEM_BYTES>>>(
        w_hi, w_hf, w_hg, w_ho, (float*)d_out);
}

// round 14
// speedup vs baseline: 1.0667x; 1.0667x over previous
#include <cuda_runtime.h>
#include <math.h>

#define S_SEQ 2048
#define NB 64
#define NH 512
#define NF 512
#define REC_THREADS 256

#define NGROUP 4                 // batch groups (16 batches each)
#define GB 16                    // batches per group
#define CTA_PER_GROUP 32         // 32 CTAs x 16 h-cols = 2048 n-cols
#define NCTA_REC (NGROUP * CTA_PER_GROUP)     // 128
#define BAR_TARGET (CTA_PER_GROUP * 8)        // 256 warp arrivals per step

// h ping-pong + per-step barrier slots (R6 design, self-cleaning).
__device__ float    g_hbuf[2][NB * NH];
__device__ unsigned g_bar[NGROUP * S_SEQ];

// -------------------------------------------------------------------------
__device__ __forceinline__ float to_tf32(float f) {
    float r;
    asm("cvt.rna.tf32.f32 %0, %1;" : "=f"(r) : "f"(f));
    return r;
}

__device__ __forceinline__ void mma_tf32(float4& c, const float* a, const float* b) {
    asm volatile(
        "mma.sync.aligned.m16n8k8.row.col.f32.tf32.tf32.f32 "
        "{%0,%1,%2,%3}, {%4,%5,%6,%7}, {%8,%9}, {%0,%1,%2,%3};"
        : "+f"(c.x), "+f"(c.y), "+f"(c.z), "+f"(c.w)
        : "r"(__float_as_uint(a[0])), "r"(__float_as_uint(a[1])),
          "r"(__float_as_uint(a[2])), "r"(__float_as_uint(a[3])),
          "r"(__float_as_uint(b[0])), "r"(__float_as_uint(b[1])));
}

__device__ __forceinline__ float fsig(float v) {
    return __fdividef(1.f, 1.f + __expf(-v));
}
__device__ __forceinline__ float ftanh(float v) {
    return 1.f - __fdividef(2.f, __expf(2.f * v) + 1.f);
}

#define CP_ASYNC16(dst_sa, src) \
    asm volatile("cp.async.cg.shared.global [%0], [%1], 16;" \
                 :: "r"(dst_sa), "l"(src))
#define CP_COMMIT() asm volatile("cp.async.commit_group;" ::: "memory")
#define CP_WAIT0()  asm volatile("cp.async.wait_group 0;" ::: "memory")

struct GatePtrs {
    const float* wx[4];   // w_ii, w_if, w_ig, w_io
    const float* wh[4];   // w_hi, w_hf, w_hg, w_ho
    const float* bx[4];
    const float* bh[4];
};

// -------------------------------------------------------------------------
// Fused LSTM, single persistent kernel (R6 rec structure + x fused).
// Per warp, slice smem holds x(t) at step start (delivered by cp.async
// issued at step t-1's tail), is consumed by x_mma, then overwritten by the
// h(t) stage for h_mma. x(t+1)'s cp.async issues right after h_mma's last
// slice read (WAR-safe: LDS results already consumed at issue).
// h path (stage/mma/dump/reduce/barrier) is bit-identical to R6.
// -------------------------------------------------------------------------
#define SLICE_STRIDE 68
#define SLICE_FLOATS (GB * SLICE_STRIDE)         // 1088 per warp
#define RED_STRIDE 68
#define RED_FLOATS (8 * GB * RED_STRIDE)         // 8704
#define WX_PER_KC (32 * 18)                      // 576 floats per kc block
#define WX_PER_WARP (8 * WX_PER_KC)              // 4608 floats
#define WX_FLOATS (8 * WX_PER_WARP)              // 36864
#define REC_SMEM_BYTES ((8 * SLICE_FLOATS + RED_FLOATS + WX_FLOATS) * 4) // 217088

__global__ __launch_bounds__(REC_THREADS, 1)
void lstm_fused_kernel(const float* __restrict__ x, GatePtrs p,
                       float* __restrict__ out) {
    extern __shared__ float sm[];
    float* red  = sm + 8 * SLICE_FLOATS;
    float* wx_s = sm + 8 * SLICE_FLOATS + RED_FLOATS;

    const int tid   = threadIdx.x;
    const int lane  = tid & 31;
    const int wid   = tid >> 5;
    const int gq    = lane >> 2;
    const int tq    = lane & 3;
    const int group = blockIdx.x >> 5;
    const int cidx  = blockIdx.x & 31;
    const int c0    = cidx * 16;
    unsigned* bar   = g_bar + group * S_SEQ;
    const bool janitor = (cidx == 0 && tid == 0);

    float* slice = sm + wid * SLICE_FLOATS;
    float* wxw   = wx_s + wid * WX_PER_WARP;
    const unsigned slice_sa =
        (unsigned)__cvta_generic_to_shared(slice);

    // ---- persistent W_h B-fragments in registers ----------------------------
    float breg[8][8][2];
#pragma unroll
    for (int nt = 0; nt < 8; ++nt) {
        const int n  = nt * 8 + gq;
        const float* wp = p.wh[n & 3] + c0 + (n >> 2);
#pragma unroll
        for (int kc = 0; kc < 8; ++kc) {
            const int k0 = wid * 64 + kc * 8 + tq;
            breg[kc][nt][0] = to_tf32(wp[(size_t)k0 * NH]);
            breg[kc][nt][1] = to_tf32(wp[(size_t)(k0 + 4) * NH]);
        }
    }

    // ---- W_x fragments into smem (R10 layout: lane stride 18, float2) ------
#pragma unroll
    for (int nt = 0; nt < 8; ++nt) {
        const int n  = nt * 8 + gq;
        const float* wp = p.wx[n & 3] + c0 + (n >> 2);
#pragma unroll
        for (int kc = 0; kc < 8; ++kc) {
            const int k0 = wid * 64 + kc * 8 + tq;
            wxw[kc * WX_PER_KC + lane * 18 + nt * 2 + 0] =
                to_tf32(wp[(size_t)k0 * NH]);
            wxw[kc * WX_PER_KC + lane * 18 + nt * 2 + 1] =
                to_tf32(wp[(size_t)(k0 + 4) * NH]);
        }
    }

    const int eb  = tid >> 4;
    const int ejj = tid & 15;
    const int gb  = group * GB + eb;
    const int ej  = c0 + ejj;
    float bias[4];
#pragma unroll
    for (int g = 0; g < 4; ++g)
        bias[g] = p.bx[g][ej] + p.bh[g][ej];
    float cst = 0.f;

    __syncthreads();   // wxw visible

    // ---- x cp.async issuer: x(s) -> this warp's slice (4 KB, 8x16B/lane) ---
    auto x_issue = [&](int s) {
#pragma unroll
        for (int it = 0; it < 8; ++it) {
            const int i   = it * 32 + lane;
            const int row = i >> 4;
            const int c4  = i & 15;
            const float* src = x + ((size_t)(group * GB + row) * S_SEQ + s) * NF
                               + wid * 64 + c4 * 4;
            CP_ASYNC16(slice_sa + (unsigned)(row * SLICE_STRIDE + c4 * 4) * 4u, src);
        }
        CP_COMMIT();
    };

    // prologue: x(0) into slice
    x_issue(0);

    for (int t = 0; t < S_SEQ; ++t) {
        float4 hr[8];
        if (t > 0) {
            // ---- wait on previous step's barrier -----------------------------
            unsigned v;
            do {
                asm volatile("ld.acquire.gpu.global.u32 %0, [%1];"
                             : "=r"(v) : "l"(bar + (t - 1)) : "memory");
            } while (v < (unsigned)BAR_TARGET);

            if (janitor && t >= 2)
                asm volatile("st.relaxed.gpu.global.u32 [%0], %1;"
                             :: "l"(bar + (t - 2)), "r"(0u) : "memory");

            // ---- h LDG prefetch (latency overlaps x_mma) ---------------------
            const float* hsrc = g_hbuf[t & 1];
#pragma unroll
            for (int it = 0; it < 8; ++it) {
                const int i   = it * 32 + lane;
                const int row = i >> 4;
                const int c4  = i & 15;
                hr[it] = __ldcg(reinterpret_cast<const float4*>(
                    hsrc + (size_t)(group * GB + row) * NH + wid * 64 + c4 * 4));
            }
        }

        // ---- x_mma: acc = x(t) @ W_x (slice holds x(t)) -----------------------
        CP_WAIT0();
        __syncwarp();
        float4 acc[8];
#pragma unroll
        for (int nt = 0; nt < 8; ++nt) acc[nt] = make_float4(0.f, 0.f, 0.f, 0.f);
#pragma unroll
        for (int kc = 0; kc < 8; ++kc) {
            const int kcol = kc * 8 + tq;
            float af[4];
            af[0] = slice[gq * SLICE_STRIDE + kcol];
            af[1] = slice[(gq + 8) * SLICE_STRIDE + kcol];
            af[2] = slice[gq * SLICE_STRIDE + kcol + 4];
            af[3] = slice[(gq + 8) * SLICE_STRIDE + kcol + 4];
            const float* wb = &wxw[kc * WX_PER_KC + lane * 18];
#pragma unroll
            for (int nt = 0; nt < 8; ++nt) {
                const float2 b = *reinterpret_cast<const float2*>(wb + nt * 2);
                float bf[2] = {b.x, b.y};
                mma_tf32(acc[nt], af, bf);
            }
        }

        if (t > 0) {
            // ---- stage h into slice (x LDS already consumed) ------------------
#pragma unroll
            for (int it = 0; it < 8; ++it) {
                const int i   = it * 32 + lane;
                const int row = i >> 4;
                const int c4  = i & 15;
                *reinterpret_cast<float4*>(&slice[row * SLICE_STRIDE + c4 * 4]) = hr[it];
            }
            __syncwarp();

            // ---- h_mma accumulate ---------------------------------------------
#pragma unroll
            for (int kc = 0; kc < 8; ++kc) {
                const int kcol = kc * 8 + tq;
                float af[4];
                af[0] = slice[gq * SLICE_STRIDE + kcol];
                af[1] = slice[(gq + 8) * SLICE_STRIDE + kcol];
                af[2] = slice[gq * SLICE_STRIDE + kcol + 4];
                af[3] = slice[(gq + 8) * SLICE_STRIDE + kcol + 4];
#pragma unroll
                for (int nt = 0; nt < 8; ++nt)
                    mma_tf32(acc[nt], af, breg[kc][nt]);
            }
        }

        // ---- dump combined partials -------------------------------------------
        {
            float* rw = red + wid * (GB * RED_STRIDE);
#pragma unroll
            for (int nt = 0; nt < 8; ++nt) {
                const int col = nt * 8 + tq * 2;
                *reinterpret_cast<float2*>(&rw[gq * RED_STRIDE + col]) =
                    make_float2(acc[nt].x, acc[nt].y);
                *reinterpret_cast<float2*>(&rw[(gq + 8) * RED_STRIDE + col]) =
                    make_float2(acc[nt].z, acc[nt].w);
            }
        }

        // ---- prefetch x(t+1) into slice (async; lands during reduce/poll) ----
        if (t + 1 < S_SEQ) x_issue(t + 1);

        __syncthreads();

        // ---- reduce 8 warp-partials + epilogue ---------------------------------
        float s0 = 0.f, s1 = 0.f, s2 = 0.f, s3 = 0.f;
#pragma unroll
        for (int w = 0; w < 8; ++w) {
            const float4 v = *reinterpret_cast<const float4*>(
                &red[(w * GB + eb) * RED_STRIDE + ejj * 4]);
            s0 += v.x; s1 += v.y; s2 += v.z; s3 += v.w;
        }

        const float ig = fsig(s0 + bias[0]);
        const float fg = fsig(s1 + bias[1]);
        const float gg = ftanh(s2 + bias[2]);
        const float og = fsig(s3 + bias[3]);
        cst = fg * cst + ig * gg;
        const float hnew = og * ftanh(cst);

        if (t < S_SEQ - 1) {
            g_hbuf[(t + 1) & 1][gb * NH + ej] = to_tf32(hnew);
            __syncwarp();
            if (lane == 0) {
                asm volatile("red.release.gpu.global.add.u32 [%0], %1;"
                             :: "l"(bar + t), "r"(1u) : "memory");
            }
        } else {
            out[gb * NH + ej]           = hnew;
            out[NB * NH + gb * NH + ej] = cst;
        }
    }

    // ---- final cleanup: extra arrival on slot S_SEQ-1, then zero -------------
    __syncwarp();
    if (lane == 0)
        asm volatile("red.release.gpu.global.add.u32 [%0], %1;"
                     :: "l"(bar + (S_SEQ - 1)), "r"(1u) : "memory");
    if (janitor) {
        unsigned v;
        do {
            asm volatile("ld.acquire.gpu.global.u32 %0, [%1];"
                         : "=r"(v) : "l"(bar + (S_SEQ - 1)) : "memory");
        } while (v < (unsigned)BAR_TARGET);
        asm volatile("st.relaxed.gpu.global.u32 [%0], %1;"
                     :: "l"(bar + (S_SEQ - 2)), "r"(0u) : "memory");
        asm volatile("st.relaxed.gpu.global.u32 [%0], %1;"
                     :: "l"(bar + (S_SEQ - 1)), "r"(0u) : "memory");
    }
}

// -------------------------------------------------------------------------
extern "C" void kernel_launch(void* const* d_in, const int* in_sizes, int n_in,
                              void* d_out, int out_size) {
    const float* x = (const float*)d_in[0];
    GatePtrs p;
    p.wx[0] = (const float*)d_in[1];   p.bx[0] = (const float*)d_in[2];
    p.wh[0] = (const float*)d_in[3];   p.bh[0] = (const float*)d_in[4];
    p.wx[1] = (const float*)d_in[5];   p.bx[1] = (const float*)d_in[6];
    p.wh[1] = (const float*)d_in[7];   p.bh[1] = (const float*)d_in[8];
    p.wx[2] = (const float*)d_in[9];   p.bx[2] = (const float*)d_in[10];
    p.wh[2] = (const float*)d_in[11];  p.bh[2] = (const float*)d_in[12];
    p.wx[3] = (const float*)d_in[13];  p.bx[3] = (const float*)d_in[14];
    p.wh[3] = (const float*)d_in[15];  p.bh[3] = (const float*)d_in[16];

    cudaFuncSetAttribute(lstm_fused_kernel, cudaFuncAttributeMaxDynamicSharedMemorySize,
                         REC_SMEM_BYTES);

    lstm_fused_kernel<<<NCTA_REC, REC_THREADS, REC_SMEM_BYTES>>>(
        x, p, (float*)d_out);
}

// round 15
// speedup vs baseline: 1.3582x; 1.2732x over previous
#include <cuda_runtime.h>
#include <cuda_fp16.h>
#include <math.h>

#define S_SEQ 2048
#define NB 64
#define NH 512
#define NF 512
#define NGATE 4
#define REC_THREADS 256

#define NGROUP 4                 // batch groups (16 batches each)
#define GB 16                    // batches per group
#define CTA_PER_GROUP 32         // 32 CTAs x 16 h-cols = 2048 n-cols
#define NCTA_REC (NGROUP * CTA_PER_GROUP)     // 128
#define BAR_TARGET (CTA_PER_GROUP * 8)        // 256 warp arrivals per step

// Scratch: pre-activations xpre[s][gate][b][h] (1.07 GB, fp32), h ping-pong
// (fp16), per-step barrier slots (R6 design, self-cleaning).
__device__ float    g_xpre[(size_t)S_SEQ * NGATE * NB * NH];
__device__ __half   g_hbuf[2][NB * NH];
__device__ unsigned g_bar[NGROUP * S_SEQ];

// -------------------------------------------------------------------------
// tf32 helpers (projection)
// -------------------------------------------------------------------------
__device__ __forceinline__ float to_tf32(float f) {
    float r;
    asm("cvt.rna.tf32.f32 %0, %1;" : "=f"(r) : "f"(f));
    return r;
}

__device__ __forceinline__ void mma_tf32(float4& c, const float* a, const float* b) {
    asm volatile(
        "mma.sync.aligned.m16n8k8.row.col.f32.tf32.tf32.f32 "
        "{%0,%1,%2,%3}, {%4,%5,%6,%7}, {%8,%9}, {%0,%1,%2,%3};"
        : "+f"(c.x), "+f"(c.y), "+f"(c.z), "+f"(c.w)
        : "r"(__float_as_uint(a[0])), "r"(__float_as_uint(a[1])),
          "r"(__float_as_uint(a[2])), "r"(__float_as_uint(a[3])),
          "r"(__float_as_uint(b[0])), "r"(__float_as_uint(b[1])));
}

// fp16 m16n8k16 mma, fp32 accumulate (recurrence)
__device__ __forceinline__ void mma_f16(float4& c, const unsigned* a,
                                        const unsigned* b) {
    asm volatile(
        "mma.sync.aligned.m16n8k16.row.col.f32.f16.f16.f32 "
        "{%0,%1,%2,%3}, {%4,%5,%6,%7}, {%8,%9}, {%0,%1,%2,%3};"
        : "+f"(c.x), "+f"(c.y), "+f"(c.z), "+f"(c.w)
        : "r"(a[0]), "r"(a[1]), "r"(a[2]), "r"(a[3]),
          "r"(b[0]), "r"(b[1]));
}

// -------------------------------------------------------------------------
// Input projection v2 (unchanged from Round 6, tf32).
// -------------------------------------------------------------------------
struct ProjPtrs {
    const float* w[4];
    const float* bx[4];
    const float* bh[4];
};

#define PROJ_THREADS 128
#define AF_FLOATS 4224
#define BS_FLOATS 4352
#define PBUF_FLOATS (AF_FLOATS + BS_FLOATS)
#define PROJ_SMEM_BYTES (2 * PBUF_FLOATS * 4)   // 68608 B

__global__ __launch_bounds__(PROJ_THREADS, 2)
void proj_tf32_kernel(const float* __restrict__ x, ProjPtrs p) {
    extern __shared__ float psm[];

    const int tid  = threadIdx.x;
    const int lane = tid & 31;
    const int wid  = tid >> 5;
    const int wm   = wid & 1;
    const int wn   = wid >> 1;
    const int gq   = lane >> 2;
    const int tq   = lane & 3;

    const int nTile = blockIdx.x;
    const int mTile = blockIdx.y;
    const int r0    = mTile * 128;
    const int g     = nTile >> 2;
    const int hc0   = (nTile & 3) * 128;
    const float* W  = p.w[g];

    float4 ga[8], gb[8];

    auto load_tile = [&](int k0) {
#pragma unroll
        for (int i = 0; i < 8; ++i) {
            const int e  = tid + i * PROJ_THREADS;
            const int ar = e >> 3, akq = e & 7;
            ga[i] = *reinterpret_cast<const float4*>(
                x + (size_t)(r0 + ar) * NF + k0 + akq * 4);
            const int br = e >> 5, bcq = e & 31;
            gb[i] = *reinterpret_cast<const float4*>(
                W + (size_t)(k0 + br) * NH + hc0 + bcq * 4);
        }
    };

    auto stage_tile = [&](int buf) {
        float* A_f = psm + buf * PBUF_FLOATS;
        float* B_s = A_f + AF_FLOATS;
#pragma unroll
        for (int i = 0; i < 8; ++i) {
            const int e   = tid + i * PROJ_THREADS;
            const int ar  = e >> 3, akq = e & 7;
            const int wmS = ar >> 6;
            const int r6  = ar & 63;
            const int mtS = r6 >> 4;
            const int half = (r6 >> 3) & 1;
            const int gqS  = r6 & 7;
            const int kcS  = akq >> 1;
            const int quad = 2 * (akq & 1) + half;
            const int base = ((wmS * 4 + mtS) * 4 + kcS) * 132 + gqS * 16 + quad;
            A_f[base + 0]  = to_tf32(ga[i].x);
            A_f[base + 4]  = to_tf32(ga[i].y);
            A_f[base + 8]  = to_tf32(ga[i].z);
            A_f[base + 12] = to_tf32(ga[i].w);

            const int br = e >> 5, bcq = e & 31;
            B_s[br * 136 + bcq * 4 + 0] = to_tf32(gb[i].x);
            B_s[br * 136 + bcq * 4 + 1] = to_tf32(gb[i].y);
            B_s[br * 136 + bcq * 4 + 2] = to_tf32(gb[i].z);
            B_s[br * 136 + bcq * 4 + 3] = to_tf32(gb[i].w);
        }
    };

    float4 acc[4][8];
#pragma unroll
    for (int mt = 0; mt < 4; ++mt)
#pragma unroll
        for (int nt = 0; nt < 8; ++nt)
            acc[mt][nt] = make_float4(0.f, 0.f, 0.f, 0.f);

    load_tile(0);
    stage_tile(0);

    for (int it = 0; it < NF / 32; ++it) {
        __syncthreads();
        if (it + 1 < NF / 32) load_tile((it + 1) * 32);

        const float* A_f = psm + (it & 1) * PBUF_FLOATS;
        const float* B_s = A_f + AF_FLOATS;
#pragma unroll
        for (int kc = 0; kc < 4; ++kc) {
            float4 afv[4];
#pragma unroll
            for (int mt = 0; mt < 4; ++mt)
                afv[mt] = *reinterpret_cast<const float4*>(
                    &A_f[((wm * 4 + mt) * 4 + kc) * 132 + lane * 4]);
            float bf[8][2];
            const int kb = kc * 8;
#pragma unroll
            for (int nt = 0; nt < 8; ++nt) {
                const int cb = wn * 64 + nt * 8 + gq;
                bf[nt][0] = B_s[(kb + tq) * 136 + cb];
                bf[nt][1] = B_s[(kb + tq + 4) * 136 + cb];
            }
#pragma unroll
            for (int mt = 0; mt < 4; ++mt)
#pragma unroll
                for (int nt = 0; nt < 8; ++nt)
                    mma_tf32(acc[mt][nt], reinterpret_cast<float*>(&afv[mt]), bf[nt]);
        }

        if (it + 1 < NF / 32) stage_tile((it + 1) & 1);
    }

#pragma unroll
    for (int nt = 0; nt < 8; ++nt) {
        const int colb = hc0 + wn * 64 + nt * 8 + tq * 2;
        const float bias0 = p.bx[g][colb]     + p.bh[g][colb];
        const float bias1 = p.bx[g][colb + 1] + p.bh[g][colb + 1];
#pragma unroll
        for (int mt = 0; mt < 4; ++mt) {
            const int r1 = r0 + wm * 64 + mt * 16 + gq;
            const int r2 = r1 + 8;
            {
                const int bb = r1 >> 11, s = r1 & 2047;
                const size_t base = ((size_t)(s * 4 + g) * NB + bb) * NH;
                *reinterpret_cast<float2*>(&g_xpre[base + colb]) =
                    make_float2(acc[mt][nt].x + bias0, acc[mt][nt].y + bias1);
            }
            {
                const int bb = r2 >> 11, s = r2 & 2047;
                const size_t base = ((size_t)(s * 4 + g) * NB + bb) * NH;
                *reinterpret_cast<float2*>(&g_xpre[base + colb]) =
                    make_float2(acc[mt][nt].z + bias0, acc[mt][nt].w + bias1);
            }
        }
    }
}

// -------------------------------------------------------------------------
// Tensor-core recurrent kernel: exact R6 structure, mma in fp16 m16n8k16.
// Warp w owns k-slice [w*64, w*64+64): stages its 16x64 fp16 h-slice
// (2 KB: 4 x LDG.128/lane), mma 4 k16-chunks x nt=8 with register-resident
// fp16 W_h fragments (64 regs). Dump/reduce fp32, barrier identical to R6.
// Slice layout: halfs, row stride 72 (4B word bank = 4*gq+tq+8*kc mod 32,
// conflict-free; 16B-aligned rows: 144 = 9*16).
// -------------------------------------------------------------------------
#define SLICE_H_STRIDE 72                        // halfs per row
#define SLICE_H (GB * SLICE_H_STRIDE)            // 1152 halfs per warp
#define RED_STRIDE 68
#define RED_FLOATS (8 * GB * RED_STRIDE)         // 8704
#define REC_SMEM_BYTES (8 * SLICE_H * 2 + RED_FLOATS * 4)   // 53248 B

__device__ __forceinline__ float fsig(float v) {
    return __fdividef(1.f, 1.f + __expf(-v));
}
__device__ __forceinline__ float ftanh(float v) {
    return 1.f - __fdividef(2.f, __expf(2.f * v) + 1.f);
}

__global__ __launch_bounds__(REC_THREADS, 1)
void rec_mma_kernel(const float* __restrict__ w_hi, const float* __restrict__ w_hf,
                    const float* __restrict__ w_hg, const float* __restrict__ w_ho,
                    float* __restrict__ out) {
    extern __shared__ float sm[];
    __half* slice_all = reinterpret_cast<__half*>(sm);
    float*  red       = sm + (8 * SLICE_H * 2) / 4;

    const int tid   = threadIdx.x;
    const int lane  = tid & 31;
    const int wid   = tid >> 5;
    const int gq    = lane >> 2;
    const int tq    = lane & 3;
    const int group = blockIdx.x >> 5;
    const int cidx  = blockIdx.x & 31;
    const int c0    = cidx * 16;
    unsigned* bar   = g_bar + group * S_SEQ;
    const bool janitor = (cidx == 0 && tid == 0);

    __half* slice = slice_all + wid * SLICE_H;

    // ---- persistent W_h B-fragments in registers (fp16, 64 regs) -----------
    // kc-th k16 chunk: b0 = {W[K0+2tq][n], W[K0+2tq+1][n]},
    //                  b1 = {W[K0+2tq+8][n], W[K0+2tq+9][n]}
    unsigned breg[4][8][2];
    {
        const float* wh[4] = {w_hi, w_hf, w_hg, w_ho};
#pragma unroll
        for (int nt = 0; nt < 8; ++nt) {
            const int n  = nt * 8 + gq;
            const float* wp = wh[n & 3] + c0 + (n >> 2);
#pragma unroll
            for (int kc = 0; kc < 4; ++kc) {
                const int K0 = wid * 64 + kc * 16;
                __half2 b0 = __floats2half2_rn(wp[(size_t)(K0 + 2 * tq) * NH],
                                               wp[(size_t)(K0 + 2 * tq + 1) * NH]);
                __half2 b1 = __floats2half2_rn(wp[(size_t)(K0 + 2 * tq + 8) * NH],
                                               wp[(size_t)(K0 + 2 * tq + 9) * NH]);
                breg[kc][nt][0] = *reinterpret_cast<unsigned*>(&b0);
                breg[kc][nt][1] = *reinterpret_cast<unsigned*>(&b1);
            }
        }
    }

    const int eb  = tid >> 4;
    const int ejj = tid & 15;
    const int gb  = group * GB + eb;
    const int ej  = c0 + ejj;
    float cst = 0.f;

    for (int t = 0; t < S_SEQ; ++t) {
        float xv[4];
#pragma unroll
        for (int g = 0; g < 4; ++g)
            xv[g] = __ldcg(&g_xpre[(((size_t)t * 4 + g) * NB + gb) * NH + ej]);

        if (t > 0) {
            // ---- wait on previous step's barrier (direct poll) --------------
            unsigned v;
            do {
                asm volatile("ld.acquire.gpu.global.u32 %0, [%1];"
                             : "=r"(v) : "l"(bar + (t - 1)) : "memory");
            } while (v < (unsigned)BAR_TARGET);

            if (janitor && t >= 2)
                asm volatile("st.relaxed.gpu.global.u32 [%0], %1;"
                             :: "l"(bar + (t - 2)), "r"(0u) : "memory");

            // ---- stage this warp's 16 x 64 fp16 h-slice (2 KB) ---------------
            const __half* hsrc = g_hbuf[t & 1];
#pragma unroll
            for (int it = 0; it < 4; ++it) {
                const int i   = it * 32 + lane;    // 0..127
                const int row = i >> 3;            // 0..15
                const int c8  = i & 7;             // 8-half chunk
                uint4 hv = __ldcg(reinterpret_cast<const uint4*>(
                    hsrc + (size_t)(group * GB + row) * NH + wid * 64 + c8 * 8));
                *reinterpret_cast<uint4*>(&slice[row * SLICE_H_STRIDE + c8 * 8]) = hv;
            }
            __syncwarp();

            // ---- fp16 mma m16 x n64: 4 k16-chunks x nt=8 ---------------------
            float4 acc[8];
#pragma unroll
            for (int nt = 0; nt < 8; ++nt) acc[nt] = make_float4(0.f, 0.f, 0.f, 0.f);

#pragma unroll
            for (int kc = 0; kc < 4; ++kc) {
                const int base = kc * 16 + tq * 2;     // halfs within row
                unsigned af[4];
                af[0] = *reinterpret_cast<const unsigned*>(
                    &slice[gq * SLICE_H_STRIDE + base]);
                af[1] = *reinterpret_cast<const unsigned*>(
                    &slice[(gq + 8) * SLICE_H_STRIDE + base]);
                af[2] = *reinterpret_cast<const unsigned*>(
                    &slice[gq * SLICE_H_STRIDE + base + 8]);
                af[3] = *reinterpret_cast<const unsigned*>(
                    &slice[(gq + 8) * SLICE_H_STRIDE + base + 8]);
#pragma unroll
                for (int nt = 0; nt < 8; ++nt)
                    mma_f16(acc[nt], af, breg[kc][nt]);
            }

            // ---- dump partials (fp32, unchanged) ------------------------------
            float* rw = red + wid * (GB * RED_STRIDE);
#pragma unroll
            for (int nt = 0; nt < 8; ++nt) {
                const int col = nt * 8 + tq * 2;
                *reinterpret_cast<float2*>(&rw[gq * RED_STRIDE + col]) =
                    make_float2(acc[nt].x, acc[nt].y);
                *reinterpret_cast<float2*>(&rw[(gq + 8) * RED_STRIDE + col]) =
                    make_float2(acc[nt].z, acc[nt].w);
            }
        }
        __syncthreads();

        // ---- reduce 8 warp-partials + epilogue --------------------------------
        float s0 = 0.f, s1 = 0.f, s2 = 0.f, s3 = 0.f;
        if (t > 0) {
#pragma unroll
            for (int w = 0; w < 8; ++w) {
                const float4 v = *reinterpret_cast<const float4*>(
                    &red[(w * GB + eb) * RED_STRIDE + ejj * 4]);
                s0 += v.x; s1 += v.y; s2 += v.z; s3 += v.w;
            }
        }

        const float ig = fsig(s0 + xv[0]);
        const float fg = fsig(s1 + xv[1]);
        const float gg = ftanh(s2 + xv[2]);
        const float og = fsig(s3 + xv[3]);
        cst = fg * cst + ig * gg;
        const float hnew = og * ftanh(cst);

        if (t < S_SEQ - 1) {
            g_hbuf[(t + 1) & 1][gb * NH + ej] = __float2half_rn(hnew);
            __syncwarp();
            if (lane == 0) {
                asm volatile("red.release.gpu.global.add.u32 [%0], %1;"
                             :: "l"(bar + t), "r"(1u) : "memory");
            }
        } else {
            out[gb * NH + ej]           = hnew;
            out[NB * NH + gb * NH + ej] = cst;
        }
    }

    // ---- final cleanup: extra arrival on slot S_SEQ-1, then zero ------------
    __syncwarp();
    if (lane == 0)
        asm volatile("red.release.gpu.global.add.u32 [%0], %1;"
                     :: "l"(bar + (S_SEQ - 1)), "r"(1u) : "memory");
    if (janitor) {
        unsigned v;
        do {
            asm volatile("ld.acquire.gpu.global.u32 %0, [%1];"
                         : "=r"(v) : "l"(bar + (S_SEQ - 1)) : "memory");
        } while (v < (unsigned)BAR_TARGET);
        asm volatile("st.relaxed.gpu.global.u32 [%0], %1;"
                     :: "l"(bar + (S_SEQ - 2)), "r"(0u) : "memory");
        asm volatile("st.relaxed.gpu.global.u32 [%0], %1;"
                     :: "l"(bar + (S_SEQ - 1)), "r"(0u) : "memory");
    }
}

// -------------------------------------------------------------------------
extern "C" void kernel_launch(void* const* d_in, const int* in_sizes, int n_in,
                              void* d_out, int out_size) {
    const float* x    = (const float*)d_in[0];
    const float* w_ii = (const float*)d_in[1];
    const float* b_ii = (const float*)d_in[2];
    const float* w_hi = (const float*)d_in[3];
    const float* b_hi = (const float*)d_in[4];
    const float* w_if = (const float*)d_in[5];
    const float* b_if = (const float*)d_in[6];
    const float* w_hf = (const float*)d_in[7];
    const float* b_hf = (const float*)d_in[8];
    const float* w_ig = (const float*)d_in[9];
    const float* b_ig = (const float*)d_in[10];
    const float* w_hg = (const float*)d_in[11];
    const float* b_hg = (const float*)d_in[12];
    const float* w_io = (const float*)d_in[13];
    const float* b_io = (const float*)d_in[14];
    const float* w_ho = (const float*)d_in[15];
    const float* b_ho = (const float*)d_in[16];

    cudaFuncSetAttribute(proj_tf32_kernel, cudaFuncAttributeMaxDynamicSharedMemorySize,
                         PROJ_SMEM_BYTES);
    cudaFuncSetAttribute(rec_mma_kernel, cudaFuncAttributeMaxDynamicSharedMemorySize,
                         REC_SMEM_BYTES);

    ProjPtrs p;
    p.w[0] = w_ii; p.w[1] = w_if; p.w[2] = w_ig; p.w[3] = w_io;
    p.bx[0] = b_ii; p.bx[1] = b_if; p.bx[2] = b_ig; p.bx[3] = b_io;
    p.bh[0] = b_hi; p.bh[1] = b_hf; p.bh[2] = b_hg; p.bh[3] = b_ho;
    proj_tf32_kernel<<<dim3(16, 1024), PROJ_THREADS, PROJ_SMEM_BYTES>>>(x, p);

    rec_mma_kernel<<<NCTA_REC, REC_THREADS, REC_SMEM_BYTES>>>(
        w_hi, w_hf, w_hg, w_ho, (float*)d_out);
}

// round 16
// speedup vs baseline: 1.4798x; 1.0896x over previous
#include <cuda_runtime.h>
#include <cuda_fp16.h>
#include <math.h>

#define S_SEQ 2048
#define NB 64
#define NH 512
#define NF 512
#define NGATE 4
#define REC_THREADS 256

#define NGROUP 4                 // batch groups (16 batches each)
#define GB 16                    // batches per group
#define CTA_PER_GROUP 32         // 32 CTAs x 16 h-cols = 2048 n-cols
#define NCTA_REC (NGROUP * CTA_PER_GROUP)     // 128
#define BAR_TARGET CTA_PER_GROUP              // 32 per-CTA arrivals per step

// Scratch: pre-activations xpre[s][gate][b][h] (1.07 GB, fp32), h ping-pong
// (fp16), per-step barrier slots (self-cleaning).
__device__ float    g_xpre[(size_t)S_SEQ * NGATE * NB * NH];
__device__ __half   g_hbuf[2][NB * NH];
__device__ unsigned g_bar[NGROUP * S_SEQ];

// -------------------------------------------------------------------------
// tf32 helpers (projection)
// -------------------------------------------------------------------------
__device__ __forceinline__ float to_tf32(float f) {
    float r;
    asm("cvt.rna.tf32.f32 %0, %1;" : "=f"(r) : "f"(f));
    return r;
}

__device__ __forceinline__ void mma_tf32(float4& c, const float* a, const float* b) {
    asm volatile(
        "mma.sync.aligned.m16n8k8.row.col.f32.tf32.tf32.f32 "
        "{%0,%1,%2,%3}, {%4,%5,%6,%7}, {%8,%9}, {%0,%1,%2,%3};"
        : "+f"(c.x), "+f"(c.y), "+f"(c.z), "+f"(c.w)
        : "r"(__float_as_uint(a[0])), "r"(__float_as_uint(a[1])),
          "r"(__float_as_uint(a[2])), "r"(__float_as_uint(a[3])),
          "r"(__float_as_uint(b[0])), "r"(__float_as_uint(b[1])));
}

// fp16 m16n8k16 mma, fp32 accumulate (recurrence)
__device__ __forceinline__ void mma_f16(float4& c, const unsigned* a,
                                        const unsigned* b) {
    asm volatile(
        "mma.sync.aligned.m16n8k16.row.col.f32.f16.f16.f32 "
        "{%0,%1,%2,%3}, {%4,%5,%6,%7}, {%8,%9}, {%0,%1,%2,%3};"
        : "+f"(c.x), "+f"(c.y), "+f"(c.z), "+f"(c.w)
        : "r"(a[0]), "r"(a[1]), "r"(a[2]), "r"(a[3]),
          "r"(b[0]), "r"(b[1]));
}

// -------------------------------------------------------------------------
// Input projection v2 (unchanged from Round 6, tf32).
// -------------------------------------------------------------------------
struct ProjPtrs {
    const float* w[4];
    const float* bx[4];
    const float* bh[4];
};

#define PROJ_THREADS 128
#define AF_FLOATS 4224
#define BS_FLOATS 4352
#define PBUF_FLOATS (AF_FLOATS + BS_FLOATS)
#define PROJ_SMEM_BYTES (2 * PBUF_FLOATS * 4)   // 68608 B

__global__ __launch_bounds__(PROJ_THREADS, 2)
void proj_tf32_kernel(const float* __restrict__ x, ProjPtrs p) {
    extern __shared__ float psm[];

    const int tid  = threadIdx.x;
    const int lane = tid & 31;
    const int wid  = tid >> 5;
    const int wm   = wid & 1;
    const int wn   = wid >> 1;
    const int gq   = lane >> 2;
    const int tq   = lane & 3;

    const int nTile = blockIdx.x;
    const int mTile = blockIdx.y;
    const int r0    = mTile * 128;
    const int g     = nTile >> 2;
    const int hc0   = (nTile & 3) * 128;
    const float* W  = p.w[g];

    float4 ga[8], gb[8];

    auto load_tile = [&](int k0) {
#pragma unroll
        for (int i = 0; i < 8; ++i) {
            const int e  = tid + i * PROJ_THREADS;
            const int ar = e >> 3, akq = e & 7;
            ga[i] = *reinterpret_cast<const float4*>(
                x + (size_t)(r0 + ar) * NF + k0 + akq * 4);
            const int br = e >> 5, bcq = e & 31;
            gb[i] = *reinterpret_cast<const float4*>(
                W + (size_t)(k0 + br) * NH + hc0 + bcq * 4);
        }
    };

    auto stage_tile = [&](int buf) {
        float* A_f = psm + buf * PBUF_FLOATS;
        float* B_s = A_f + AF_FLOATS;
#pragma unroll
        for (int i = 0; i < 8; ++i) {
            const int e   = tid + i * PROJ_THREADS;
            const int ar  = e >> 3, akq = e & 7;
            const int wmS = ar >> 6;
            const int r6  = ar & 63;
            const int mtS = r6 >> 4;
            const int half = (r6 >> 3) & 1;
            const int gqS  = r6 & 7;
            const int kcS  = akq >> 1;
            const int quad = 2 * (akq & 1) + half;
            const int base = ((wmS * 4 + mtS) * 4 + kcS) * 132 + gqS * 16 + quad;
            A_f[base + 0]  = to_tf32(ga[i].x);
            A_f[base + 4]  = to_tf32(ga[i].y);
            A_f[base + 8]  = to_tf32(ga[i].z);
            A_f[base + 12] = to_tf32(ga[i].w);

            const int br = e >> 5, bcq = e & 31;
            B_s[br * 136 + bcq * 4 + 0] = to_tf32(gb[i].x);
            B_s[br * 136 + bcq * 4 + 1] = to_tf32(gb[i].y);
            B_s[br * 136 + bcq * 4 + 2] = to_tf32(gb[i].z);
            B_s[br * 136 + bcq * 4 + 3] = to_tf32(gb[i].w);
        }
    };

    float4 acc[4][8];
#pragma unroll
    for (int mt = 0; mt < 4; ++mt)
#pragma unroll
        for (int nt = 0; nt < 8; ++nt)
            acc[mt][nt] = make_float4(0.f, 0.f, 0.f, 0.f);

    load_tile(0);
    stage_tile(0);

    for (int it = 0; it < NF / 32; ++it) {
        __syncthreads();
        if (it + 1 < NF / 32) load_tile((it + 1) * 32);

        const float* A_f = psm + (it & 1) * PBUF_FLOATS;
        const float* B_s = A_f + AF_FLOATS;
#pragma unroll
        for (int kc = 0; kc < 4; ++kc) {
            float4 afv[4];
#pragma unroll
            for (int mt = 0; mt < 4; ++mt)
                afv[mt] = *reinterpret_cast<const float4*>(
                    &A_f[((wm * 4 + mt) * 4 + kc) * 132 + lane * 4]);
            float bf[8][2];
            const int kb = kc * 8;
#pragma unroll
            for (int nt = 0; nt < 8; ++nt) {
                const int cb = wn * 64 + nt * 8 + gq;
                bf[nt][0] = B_s[(kb + tq) * 136 + cb];
                bf[nt][1] = B_s[(kb + tq + 4) * 136 + cb];
            }
#pragma unroll
            for (int mt = 0; mt < 4; ++mt)
#pragma unroll
                for (int nt = 0; nt < 8; ++nt)
                    mma_tf32(acc[mt][nt], reinterpret_cast<float*>(&afv[mt]), bf[nt]);
        }

        if (it + 1 < NF / 32) stage_tile((it + 1) & 1);
    }

#pragma unroll
    for (int nt = 0; nt < 8; ++nt) {
        const int colb = hc0 + wn * 64 + nt * 8 + tq * 2;
        const float bias0 = p.bx[g][colb]     + p.bh[g][colb];
        const float bias1 = p.bx[g][colb + 1] + p.bh[g][colb + 1];
#pragma unroll
        for (int mt = 0; mt < 4; ++mt) {
            const int r1 = r0 + wm * 64 + mt * 16 + gq;
            const int r2 = r1 + 8;
            {
                const int bb = r1 >> 11, s = r1 & 2047;
                const size_t base = ((size_t)(s * 4 + g) * NB + bb) * NH;
                *reinterpret_cast<float2*>(&g_xpre[base + colb]) =
                    make_float2(acc[mt][nt].x + bias0, acc[mt][nt].y + bias1);
            }
            {
                const int bb = r2 >> 11, s = r2 & 2047;
                const size_t base = ((size_t)(s * 4 + g) * NB + bb) * NH;
                *reinterpret_cast<float2*>(&g_xpre[base + colb]) =
                    make_float2(acc[mt][nt].z + bias0, acc[mt][nt].w + bias1);
            }
        }
    }
}

// -------------------------------------------------------------------------
// Tensor-core recurrent kernel: R15 fp16 structure, PER-CTA barrier arrival.
// After the epilogue stores, one __syncthreads() (consumers needed all 256
// threads done anyway) and thread 0 alone releases -> 32 arrivals/step per
// group instead of 256 (8x less atomic traffic on the hot barrier line;
// poll side unchanged: every warp polls directly, R6/R15-proven).
// -------------------------------------------------------------------------
#define SLICE_H_STRIDE 72                        // halfs per row
#define SLICE_H (GB * SLICE_H_STRIDE)            // 1152 halfs per warp
#define RED_STRIDE 68
#define RED_FLOATS (8 * GB * RED_STRIDE)         // 8704
#define REC_SMEM_BYTES (8 * SLICE_H * 2 + RED_FLOATS * 4)   // 53248 B

__device__ __forceinline__ float fsig(float v) {
    return __fdividef(1.f, 1.f + __expf(-v));
}
__device__ __forceinline__ float ftanh(float v) {
    return 1.f - __fdividef(2.f, __expf(2.f * v) + 1.f);
}

__global__ __launch_bounds__(REC_THREADS, 1)
void rec_mma_kernel(const float* __restrict__ w_hi, const float* __restrict__ w_hf,
                    const float* __restrict__ w_hg, const float* __restrict__ w_ho,
                    float* __restrict__ out) {
    extern __shared__ float sm[];
    __half* slice_all = reinterpret_cast<__half*>(sm);
    float*  red       = sm + (8 * SLICE_H * 2) / 4;

    const int tid   = threadIdx.x;
    const int lane  = tid & 31;
    const int wid   = tid >> 5;
    const int gq    = lane >> 2;
    const int tq    = lane & 3;
    const int group = blockIdx.x >> 5;
    const int cidx  = blockIdx.x & 31;
    const int c0    = cidx * 16;
    unsigned* bar   = g_bar + group * S_SEQ;
    const bool janitor = (cidx == 0 && tid == 0);

    __half* slice = slice_all + wid * SLICE_H;

    // ---- persistent W_h B-fragments in registers (fp16, 64 regs) -----------
    unsigned breg[4][8][2];
    {
        const float* wh[4] = {w_hi, w_hf, w_hg, w_ho};
#pragma unroll
        for (int nt = 0; nt < 8; ++nt) {
            const int n  = nt * 8 + gq;
            const float* wp = wh[n & 3] + c0 + (n >> 2);
#pragma unroll
            for (int kc = 0; kc < 4; ++kc) {
                const int K0 = wid * 64 + kc * 16;
                __half2 b0 = __floats2half2_rn(wp[(size_t)(K0 + 2 * tq) * NH],
                                               wp[(size_t)(K0 + 2 * tq + 1) * NH]);
                __half2 b1 = __floats2half2_rn(wp[(size_t)(K0 + 2 * tq + 8) * NH],
                                               wp[(size_t)(K0 + 2 * tq + 9) * NH]);
                breg[kc][nt][0] = *reinterpret_cast<unsigned*>(&b0);
                breg[kc][nt][1] = *reinterpret_cast<unsigned*>(&b1);
            }
        }
    }

    const int eb  = tid >> 4;
    const int ejj = tid & 15;
    const int gb  = group * GB + eb;
    const int ej  = c0 + ejj;
    float cst = 0.f;

    for (int t = 0; t < S_SEQ; ++t) {
        float xv[4];
#pragma unroll
        for (int g = 0; g < 4; ++g)
            xv[g] = __ldcg(&g_xpre[(((size_t)t * 4 + g) * NB + gb) * NH + ej]);

        if (t > 0) {
            // ---- wait on previous step's barrier (direct poll) --------------
            unsigned v;
            do {
                asm volatile("ld.acquire.gpu.global.u32 %0, [%1];"
                             : "=r"(v) : "l"(bar + (t - 1)) : "memory");
            } while (v < (unsigned)BAR_TARGET);

            if (janitor && t >= 2)
                asm volatile("st.relaxed.gpu.global.u32 [%0], %1;"
                             :: "l"(bar + (t - 2)), "r"(0u) : "memory");

            // ---- stage this warp's 16 x 64 fp16 h-slice (2 KB) ---------------
            const __half* hsrc = g_hbuf[t & 1];
#pragma unroll
            for (int it = 0; it < 4; ++it) {
                const int i   = it * 32 + lane;    // 0..127
                const int row = i >> 3;            // 0..15
                const int c8  = i & 7;             // 8-half chunk
                uint4 hv = __ldcg(reinterpret_cast<const uint4*>(
                    hsrc + (size_t)(group * GB + row) * NH + wid * 64 + c8 * 8));
                *reinterpret_cast<uint4*>(&slice[row * SLICE_H_STRIDE + c8 * 8]) = hv;
            }
            __syncwarp();

            // ---- fp16 mma m16 x n64: 4 k16-chunks x nt=8 ---------------------
            float4 acc[8];
#pragma unroll
            for (int nt = 0; nt < 8; ++nt) acc[nt] = make_float4(0.f, 0.f, 0.f, 0.f);

#pragma unroll
            for (int kc = 0; kc < 4; ++kc) {
                const int base = kc * 16 + tq * 2;     // halfs within row
                unsigned af[4];
                af[0] = *reinterpret_cast<const unsigned*>(
                    &slice[gq * SLICE_H_STRIDE + base]);
                af[1] = *reinterpret_cast<const unsigned*>(
                    &slice[(gq + 8) * SLICE_H_STRIDE + base]);
                af[2] = *reinterpret_cast<const unsigned*>(
                    &slice[gq * SLICE_H_STRIDE + base + 8]);
                af[3] = *reinterpret_cast<const unsigned*>(
                    &slice[(gq + 8) * SLICE_H_STRIDE + base + 8]);
#pragma unroll
                for (int nt = 0; nt < 8; ++nt)
                    mma_f16(acc[nt], af, breg[kc][nt]);
            }

            // ---- dump partials (fp32) ------------------------------------------
            float* rw = red + wid * (GB * RED_STRIDE);
#pragma unroll
            for (int nt = 0; nt < 8; ++nt) {
                const int col = nt * 8 + tq * 2;
                *reinterpret_cast<float2*>(&rw[gq * RED_STRIDE + col]) =
                    make_float2(acc[nt].x, acc[nt].y);
                *reinterpret_cast<float2*>(&rw[(gq + 8) * RED_STRIDE + col]) =
                    make_float2(acc[nt].z, acc[nt].w);
            }
        }
        __syncthreads();

        // ---- reduce 8 warp-partials + epilogue --------------------------------
        float s0 = 0.f, s1 = 0.f, s2 = 0.f, s3 = 0.f;
        if (t > 0) {
#pragma unroll
            for (int w = 0; w < 8; ++w) {
                const float4 v = *reinterpret_cast<const float4*>(
                    &red[(w * GB + eb) * RED_STRIDE + ejj * 4]);
                s0 += v.x; s1 += v.y; s2 += v.z; s3 += v.w;
            }
        }

        const float ig = fsig(s0 + xv[0]);
        const float fg = fsig(s1 + xv[1]);
        const float gg = ftanh(s2 + xv[2]);
        const float og = fsig(s3 + xv[3]);
        cst = fg * cst + ig * gg;
        const float hnew = og * ftanh(cst);

        if (t < S_SEQ - 1) {
            g_hbuf[(t + 1) & 1][gb * NH + ej] = __float2half_rn(hnew);
            // ---- per-CTA arrival: all stores done, thread 0 releases ----------
            __syncthreads();
            if (tid == 0) {
                asm volatile("red.release.gpu.global.add.u32 [%0], %1;"
                             :: "l"(bar + t), "r"(1u) : "memory");
            }
        } else {
            out[gb * NH + ej]           = hnew;
            out[NB * NH + gb * NH + ej] = cst;
        }
    }

    // ---- final cleanup: one extra per-CTA arrival on slot S_SEQ-1 -----------
    __syncthreads();
    if (tid == 0)
        asm volatile("red.release.gpu.global.add.u32 [%0], %1;"
                     :: "l"(bar + (S_SEQ - 1)), "r"(1u) : "memory");
    if (janitor) {
        unsigned v;
        do {
            asm volatile("ld.acquire.gpu.global.u32 %0, [%1];"
                         : "=r"(v) : "l"(bar + (S_SEQ - 1)) : "memory");
        } while (v < (unsigned)BAR_TARGET);
        asm volatile("st.relaxed.gpu.global.u32 [%0], %1;"
                     :: "l"(bar + (S_SEQ - 2)), "r"(0u) : "memory");
        asm volatile("st.relaxed.gpu.global.u32 [%0], %1;"
                     :: "l"(bar + (S_SEQ - 1)), "r"(0u) : "memory");
    }
}

// -------------------------------------------------------------------------
extern "C" void kernel_launch(void* const* d_in, const int* in_sizes, int n_in,
                              void* d_out, int out_size) {
    const float* x    = (const float*)d_in[0];
    const float* w_ii = (const float*)d_in[1];
    const float* b_ii = (const float*)d_in[2];
    const float* w_hi = (const float*)d_in[3];
    const float* b_hi = (const float*)d_in[4];
    const float* w_if = (const float*)d_in[5];
    const float* b_if = (const float*)d_in[6];
    const float* w_hf = (const float*)d_in[7];
    const float* b_hf = (const float*)d_in[8];
    const float* w_ig = (const float*)d_in[9];
    const float* b_ig = (const float*)d_in[10];
    const float* w_hg = (const float*)d_in[11];
    const float* b_hg = (const float*)d_in[12];
    const float* w_io = (const float*)d_in[13];
    const float* b_io = (const float*)d_in[14];
    const float* w_ho = (const float*)d_in[15];
    const float* b_ho = (const float*)d_in[16];

    cudaFuncSetAttribute(proj_tf32_kernel, cudaFuncAttributeMaxDynamicSharedMemorySize,
                         PROJ_SMEM_BYTES);
    cudaFuncSetAttribute(rec_mma_kernel, cudaFuncAttributeMaxDynamicSharedMemorySize,
                         REC_SMEM_BYTES);

    ProjPtrs p;
    p.w[0] = w_ii; p.w[1] = w_if; p.w[2] = w_ig; p.w[3] = w_io;
    p.bx[0] = b_ii; p.bx[1] = b_if; p.bx[2] = b_ig; p.bx[3] = b_io;
    p.bh[0] = b_hi; p.bh[1] = b_hf; p.bh[2] = b_hg; p.bh[3] = b_ho;
    proj_tf32_kernel<<<dim3(16, 1024), PROJ_THREADS, PROJ_SMEM_BYTES>>>(x, p);

    rec_mma_kernel<<<NCTA_REC, REC_THREADS, REC_SMEM_BYTES>>>(
        w_hi, w_hf, w_hg, w_ho, (float*)d_out);
}